// round 5
// baseline (speedup 1.0000x reference)
#include <cuda_runtime.h>

#define N_NODES 500000
#define N_EDGES 16000000

#define NODE_TB 256
#define NODE_GRID 1024      // k_node blocks
#define NPART NODE_GRID

// ---- device scratch (no allocations allowed; __device__ statics only) ----
__device__ int    g_idx64;            // 1 if edge_index is int64, 0 if int32
__device__ float  g_deg[N_NODES];     // 1 + sum of incoming edge weights
__device__ float  g_dis[N_NODES];     // rsqrt(deg)
__device__ float  g_q[N_NODES];       // dis * x
__device__ float  g_acc[N_NODES];     // sum_{e->d} ew * q[src]
__device__ float  g_u[N_NODES];       // sum_{e from s} ew * dis[dst]
__device__ double g_part0[NPART];     // per-block partial sums, channel 0
__device__ double g_part1[NPART];     // per-block partial sums, channel 1

// ---------------------------------------------------------------- dtype detect
__global__ void k_detect(const int* __restrict__ eiw) {
    int all_zero = 1;
    #pragma unroll
    for (int k = 0; k < 8; k++) all_zero &= (eiw[2 * k + 1] == 0);
    g_idx64 = all_zero;
}

// ---------------------------------------------------------------- init
__global__ void k_init() {
    int i = blockIdx.x * blockDim.x + threadIdx.x;
    if (i < N_NODES) { g_deg[i] = 1.0f; g_acc[i] = 0.0f; g_u[i] = 0.0f; }
}

// ---------------------------------------------------------------- pass 1: degree (4 edges/thread)
__global__ void k_deg(const void* __restrict__ ei, const float4* __restrict__ ew4) {
    int t = blockIdx.x * blockDim.x + threadIdx.x;   // t < N_EDGES/4 exactly
    float4 w = ew4[t];
    int d0, d1, d2, d3;
    if (!g_idx64) {
        int4 d = ((const int4*)ei)[N_EDGES / 4 + t];          // row 1 = dst
        d0 = d.x; d1 = d.y; d2 = d.z; d3 = d.w;
    } else {
        const long long* dst = (const long long*)ei + N_EDGES;
        longlong2 a = ((const longlong2*)dst)[2 * t];
        longlong2 b = ((const longlong2*)dst)[2 * t + 1];
        d0 = (int)a.x; d1 = (int)a.y; d2 = (int)b.x; d3 = (int)b.y;
    }
    if ((unsigned)d0 < N_NODES) atomicAdd(&g_deg[d0], w.x);
    if ((unsigned)d1 < N_NODES) atomicAdd(&g_deg[d1], w.y);
    if ((unsigned)d2 < N_NODES) atomicAdd(&g_deg[d2], w.z);
    if ((unsigned)d3 < N_NODES) atomicAdd(&g_deg[d3], w.w);
}

// ---------------------------------------------------------------- node: dis, q
__global__ void k_dis(const float* __restrict__ x) {
    int i = blockIdx.x * blockDim.x + threadIdx.x;
    if (i < N_NODES) {
        float s = rsqrtf(g_deg[i]);     // deg >= 1 (self-loop weight 1)
        g_dis[i] = s;
        g_q[i]   = s * x[i];
    }
}

// ---------------------------------------------------------------- pass 2 (fused): acc[d] += ew*q[s], u[s] += ew*dis[d]
__global__ void k_msg(const void* __restrict__ ei, const float4* __restrict__ ew4) {
    int t = blockIdx.x * blockDim.x + threadIdx.x;
    float4 w = ew4[t];
    int s0, s1, s2, s3, d0, d1, d2, d3;
    if (!g_idx64) {
        int4 s = ((const int4*)ei)[t];                        // row 0 = src
        int4 d = ((const int4*)ei)[N_EDGES / 4 + t];          // row 1 = dst
        s0 = s.x; s1 = s.y; s2 = s.z; s3 = s.w;
        d0 = d.x; d1 = d.y; d2 = d.z; d3 = d.w;
    } else {
        const long long* src = (const long long*)ei;
        const long long* dst = src + N_EDGES;
        longlong2 sa = ((const longlong2*)src)[2 * t];
        longlong2 sb = ((const longlong2*)src)[2 * t + 1];
        longlong2 da = ((const longlong2*)dst)[2 * t];
        longlong2 db = ((const longlong2*)dst)[2 * t + 1];
        s0 = (int)sa.x; s1 = (int)sa.y; s2 = (int)sb.x; s3 = (int)sb.y;
        d0 = (int)da.x; d1 = (int)da.y; d2 = (int)db.x; d3 = (int)db.y;
    }
    bool vs0 = (unsigned)s0 < N_NODES, vs1 = (unsigned)s1 < N_NODES;
    bool vs2 = (unsigned)s2 < N_NODES, vs3 = (unsigned)s3 < N_NODES;
    bool vd0 = (unsigned)d0 < N_NODES, vd1 = (unsigned)d1 < N_NODES;
    bool vd2 = (unsigned)d2 < N_NODES, vd3 = (unsigned)d3 < N_NODES;
    // 8 independent gathers first (L1tex wavefronts, overlap L2 latency)
    float q0 = vs0 ? g_q[s0] : 0.0f;
    float q1 = vs1 ? g_q[s1] : 0.0f;
    float q2 = vs2 ? g_q[s2] : 0.0f;
    float q3 = vs3 ? g_q[s3] : 0.0f;
    float c0 = vd0 ? g_dis[d0] : 0.0f;
    float c1 = vd1 ? g_dis[d1] : 0.0f;
    float c2 = vd2 ? g_dis[d2] : 0.0f;
    float c3 = vd3 ? g_dis[d3] : 0.0f;
    // 8 fire-and-forget REDs (LTS atomic slots)
    if (vd0) atomicAdd(&g_acc[d0], w.x * q0);
    if (vd1) atomicAdd(&g_acc[d1], w.y * q1);
    if (vd2) atomicAdd(&g_acc[d2], w.z * q2);
    if (vd3) atomicAdd(&g_acc[d3], w.w * q3);
    if (vs0) atomicAdd(&g_u[s0], w.x * c0);
    if (vs1) atomicAdd(&g_u[s1], w.y * c1);
    if (vs2) atomicAdd(&g_u[s2], w.z * c2);
    if (vs3) atomicAdd(&g_u[s3], w.w * c3);
}

// ---------------------------------------------------------------- shared-mem double tree reduce
__device__ __forceinline__ void block_reduce_store(float a0, float a1, int slot) {
    __shared__ double sm0[NODE_TB], sm1[NODE_TB];
    int t = threadIdx.x;
    sm0[t] = (double)a0;
    sm1[t] = (double)a1;
    __syncthreads();
    #pragma unroll
    for (int s = NODE_TB / 2; s > 0; s >>= 1) {
        if (t < s) { sm0[t] += sm0[t + s]; sm1[t] += sm1[t + s]; }
        __syncthreads();
    }
    if (t == 0) { g_part0[slot] = sm0[0]; g_part1[slot] = sm1[0]; }
}

// ---------------------------------------------------------------- node: MLP + full per-node contribution
// total contribution of node i to s[c]: h2[i,c] * (1/deg_i  +  dis_i * u_i)
__global__ void k_node(const float* __restrict__ x, const float* __restrict__ W1,
                       const float* __restrict__ b1, const float* __restrict__ W2) {
    __shared__ float sW1[16], sb1[16], sW2[32];
    int t = threadIdx.x;
    if (t < 16) { sW1[t] = W1[t]; sb1[t] = b1[t]; }
    if (t < 32) sW2[t] = W2[t];
    __syncthreads();

    float a0 = 0.0f, a1 = 0.0f;
    int stride = gridDim.x * blockDim.x;
    for (int i = blockIdx.x * blockDim.x + t; i < N_NODES; i += stride) {
        float dis = g_dis[i];
        float inv = dis * dis;                         // 1/deg
        float agg = dis * g_acc[i] + x[i] * inv;       // layer-1 scalar aggregate
        float h0 = 0.0f, h1 = 0.0f;
        #pragma unroll
        for (int j = 0; j < 16; j++) {
            float h = fmaxf(fmaf(sW1[j], agg, sb1[j]), 0.0f);
            h0 = fmaf(h, sW2[2 * j],     h0);
            h1 = fmaf(h, sW2[2 * j + 1], h1);
        }
        float coef = fmaf(dis, g_u[i], inv);           // self + edge weight of this node
        a0 = fmaf(coef, h0, a0);
        a1 = fmaf(coef, h1, a1);
    }
    block_reduce_store(a0, a1, blockIdx.x);
}

// ---------------------------------------------------------------- final: reduce partials, bias, softmax
__global__ void k_final(const float* __restrict__ b2, float* __restrict__ out) {
    __shared__ double sm0[256], sm1[256];
    int t = threadIdx.x;
    double s0 = 0.0, s1 = 0.0;
    for (int k = t; k < NPART; k += 256) { s0 += g_part0[k]; s1 += g_part1[k]; }
    sm0[t] = s0; sm1[t] = s1;
    __syncthreads();
    #pragma unroll
    for (int s = 128; s > 0; s >>= 1) {
        if (t < s) { sm0[t] += sm0[t + s]; sm1[t] += sm1[t + s]; }
        __syncthreads();
    }
    if (t == 0) {
        double v0 = sm0[0] + (double)N_NODES * (double)b2[0];
        double v1 = sm1[0] + (double)N_NODES * (double)b2[1];
        double m  = fmax(v0, v1);
        double e0 = exp(v0 - m), e1 = exp(v1 - m);
        double den = e0 + e1;
        out[0] = (float)(e0 / den);
        out[1] = (float)(e1 / den);
    }
}

// ---------------------------------------------------------------- launch
extern "C" void kernel_launch(void* const* d_in, const int* in_sizes, int n_in,
                              void* d_out, int out_size) {
    const float* x  = (const float*)d_in[0];
    const void*  ei = d_in[1];                 // int32 OR int64, detected on device
    const float* ew = (const float*)d_in[2];
    const float* W1 = (const float*)d_in[3];
    const float* b1 = (const float*)d_in[4];
    const float* W2 = (const float*)d_in[5];
    const float* b2 = (const float*)d_in[6];

    const int TB = 256;
    const int nodeBlocks  = (N_NODES + TB - 1) / TB;        // 1954
    const int edge4Blocks = (N_EDGES / 4) / TB;             // 15625 exact

    k_detect<<<1, 1>>>((const int*)ei);
    k_init  <<<nodeBlocks, TB>>>();
    k_deg   <<<edge4Blocks, TB>>>(ei, (const float4*)ew);
    k_dis   <<<nodeBlocks, TB>>>(x);
    k_msg   <<<edge4Blocks, TB>>>(ei, (const float4*)ew);
    k_node  <<<NODE_GRID, NODE_TB>>>(x, W1, b1, W2);
    k_final <<<1, 256>>>(b2, (float*)d_out);
}

// round 6
// speedup vs baseline: 1.2206x; 1.2206x over previous
#include <cuda_runtime.h>

#define N_NODES 500000
#define N_EDGES 16000000

#define NODE_TB 256
#define NODE_GRID 1024                      // k_node blocks
#define EDGE4_GRID (N_EDGES / 4 / 256)      // 15625, exact
#define NPART (NODE_GRID + EDGE4_GRID)

// ---- device scratch (no allocations allowed; __device__ statics only) ----
// g_deg / g_acc are SELF-CLEANING: zero-initialized at load, read-then-zeroed
// by k_dis / k_node each launch, so every call sees the same initial state.
__device__ int    g_idx64;            // 1 if edge_index is int64, 0 if int32
__device__ float  g_deg[N_NODES];     // edge-weight in-sums (self-loop +1 added at read)
__device__ float  g_dis[N_NODES];     // rsqrt(deg)
__device__ float  g_q[N_NODES];       // dis * x
__device__ float  g_acc[N_NODES];     // sum_{e->d} ew * q[src]
__device__ float2 g_p[N_NODES];       // dis * h2  (2 channels)
__device__ double g_part0[NPART];     // per-block partial sums, channel 0
__device__ double g_part1[NPART];     // per-block partial sums, channel 1

// ---------------------------------------------------------------- dtype detect
__global__ void k_detect(const int* __restrict__ eiw) {
    int all_zero = 1;
    #pragma unroll
    for (int k = 0; k < 8; k++) all_zero &= (eiw[2 * k + 1] == 0);
    g_idx64 = all_zero;
}

// ---------------------------------------------------------------- index fetch (4 at a time, streaming)
__device__ __forceinline__ void load_idx4(const void* ei, int row, int t,
                                          int& i0, int& i1, int& i2, int& i3) {
    if (!g_idx64) {
        int4 v = __ldcs((const int4*)ei + (size_t)row * (N_EDGES / 4) + t);
        i0 = v.x; i1 = v.y; i2 = v.z; i3 = v.w;
    } else {
        const longlong2* p = (const longlong2*)((const long long*)ei + (size_t)row * N_EDGES);
        longlong2 a = __ldcs(p + 2 * t);
        longlong2 b = __ldcs(p + 2 * t + 1);
        i0 = (int)a.x; i1 = (int)a.y; i2 = (int)b.x; i3 = (int)b.y;
    }
}

// ---------------------------------------------------------------- pass 1: degree (4 edges/thread)
__global__ void k_deg(const void* __restrict__ ei, const float4* __restrict__ ew4) {
    int t = blockIdx.x * blockDim.x + threadIdx.x;   // t < N_EDGES/4 exactly
    float4 w = __ldcs(ew4 + t);
    int d0, d1, d2, d3;
    load_idx4(ei, 1, t, d0, d1, d2, d3);
    if ((unsigned)d0 < N_NODES) atomicAdd(&g_deg[d0], w.x);
    if ((unsigned)d1 < N_NODES) atomicAdd(&g_deg[d1], w.y);
    if ((unsigned)d2 < N_NODES) atomicAdd(&g_deg[d2], w.z);
    if ((unsigned)d3 < N_NODES) atomicAdd(&g_deg[d3], w.w);
}

// ---------------------------------------------------------------- node: dis, q (+ reset deg)
__global__ void k_dis(const float* __restrict__ x) {
    int i = blockIdx.x * blockDim.x + threadIdx.x;
    if (i < N_NODES) {
        float dv = g_deg[i];
        g_deg[i] = 0.0f;                       // self-clean for next launch
        float s = rsqrtf(dv + 1.0f);           // +1 = self-loop weight
        g_dis[i] = s;
        g_q[i]   = s * x[i];
    }
}

// ---------------------------------------------------------------- pass 2: acc[d] += ew * q[s] (4 edges/thread)
__global__ void k_msg(const void* __restrict__ ei, const float4* __restrict__ ew4) {
    int t = blockIdx.x * blockDim.x + threadIdx.x;
    float4 w = __ldcs(ew4 + t);
    int s0, s1, s2, s3, d0, d1, d2, d3;
    load_idx4(ei, 0, t, s0, s1, s2, s3);
    load_idx4(ei, 1, t, d0, d1, d2, d3);
    // independent gathers first (overlap L2 latency), then REDs
    float q0 = ((unsigned)s0 < N_NODES) ? g_q[s0] : 0.0f;
    float q1 = ((unsigned)s1 < N_NODES) ? g_q[s1] : 0.0f;
    float q2 = ((unsigned)s2 < N_NODES) ? g_q[s2] : 0.0f;
    float q3 = ((unsigned)s3 < N_NODES) ? g_q[s3] : 0.0f;
    if ((unsigned)d0 < N_NODES) atomicAdd(&g_acc[d0], w.x * q0);
    if ((unsigned)d1 < N_NODES) atomicAdd(&g_acc[d1], w.y * q1);
    if ((unsigned)d2 < N_NODES) atomicAdd(&g_acc[d2], w.z * q2);
    if ((unsigned)d3 < N_NODES) atomicAdd(&g_acc[d3], w.w * q3);
}

// ---------------------------------------------------------------- shared-mem double tree reduce
__device__ __forceinline__ void block_reduce_store(float a0, float a1, int slot) {
    __shared__ double sm0[NODE_TB], sm1[NODE_TB];
    int t = threadIdx.x;
    sm0[t] = (double)a0;
    sm1[t] = (double)a1;
    __syncthreads();
    #pragma unroll
    for (int s = NODE_TB / 2; s > 0; s >>= 1) {
        if (t < s) { sm0[t] += sm0[t + s]; sm1[t] += sm1[t + s]; }
        __syncthreads();
    }
    if (t == 0) { g_part0[slot] = sm0[0]; g_part1[slot] = sm1[0]; }
}

// ---------------------------------------------------------------- node: MLP + self terms (+ reset acc)
__global__ void k_node(const float* __restrict__ x, const float* __restrict__ W1,
                       const float* __restrict__ b1, const float* __restrict__ W2) {
    __shared__ float sW1[16], sb1[16], sW2[32];
    int t = threadIdx.x;
    if (t < 16) { sW1[t] = W1[t]; sb1[t] = b1[t]; }
    if (t < 32) sW2[t] = W2[t];
    __syncthreads();

    float a0 = 0.0f, a1 = 0.0f;
    int stride = gridDim.x * blockDim.x;
    for (int i = blockIdx.x * blockDim.x + t; i < N_NODES; i += stride) {
        float ac = g_acc[i];
        g_acc[i] = 0.0f;                           // self-clean for next launch
        float dis = g_dis[i];
        float inv = dis * dis;                     // 1/deg
        float agg = dis * ac + x[i] * inv;         // layer-1 scalar aggregate
        float h0 = 0.0f, h1 = 0.0f;
        #pragma unroll
        for (int j = 0; j < 16; j++) {
            float h = fmaxf(fmaf(sW1[j], agg, sb1[j]), 0.0f);
            h0 = fmaf(h, sW2[2 * j],     h0);
            h1 = fmaf(h, sW2[2 * j + 1], h1);
        }
        g_p[i] = make_float2(dis * h0, dis * h1);
        a0 = fmaf(inv, h0, a0);                    // self-loop term of final sum
        a1 = fmaf(inv, h1, a1);
    }
    block_reduce_store(a0, a1, blockIdx.x);
}

// ---------------------------------------------------------------- pass 3: edge term of final sum (4 edges/thread, direct map)
__global__ void k_edge2(const void* __restrict__ ei, const float4* __restrict__ ew4) {
    int t = blockIdx.x * blockDim.x + threadIdx.x;   // t < N_EDGES/4 exactly
    float4 w = __ldcs(ew4 + t);
    int s0, s1, s2, s3, d0, d1, d2, d3;
    load_idx4(ei, 0, t, s0, s1, s2, s3);
    load_idx4(ei, 1, t, d0, d1, d2, d3);
    float2 p0 = ((unsigned)s0 < N_NODES) ? g_p[s0] : make_float2(0.f, 0.f);
    float2 p1 = ((unsigned)s1 < N_NODES) ? g_p[s1] : make_float2(0.f, 0.f);
    float2 p2 = ((unsigned)s2 < N_NODES) ? g_p[s2] : make_float2(0.f, 0.f);
    float2 p3 = ((unsigned)s3 < N_NODES) ? g_p[s3] : make_float2(0.f, 0.f);
    float c0 = ((unsigned)d0 < N_NODES) ? w.x * g_dis[d0] : 0.0f;
    float c1 = ((unsigned)d1 < N_NODES) ? w.y * g_dis[d1] : 0.0f;
    float c2 = ((unsigned)d2 < N_NODES) ? w.z * g_dis[d2] : 0.0f;
    float c3 = ((unsigned)d3 < N_NODES) ? w.w * g_dis[d3] : 0.0f;
    float a0 = c0 * p0.x + c1 * p1.x + c2 * p2.x + c3 * p3.x;
    float a1 = c0 * p0.y + c1 * p1.y + c2 * p2.y + c3 * p3.y;
    block_reduce_store(a0, a1, NODE_GRID + blockIdx.x);
}

// ---------------------------------------------------------------- final: reduce partials, bias, softmax
__global__ void k_final(const float* __restrict__ b2, float* __restrict__ out) {
    __shared__ double sm0[256], sm1[256];
    int t = threadIdx.x;
    double s0 = 0.0, s1 = 0.0;
    for (int k = t; k < NPART; k += 256) { s0 += g_part0[k]; s1 += g_part1[k]; }
    sm0[t] = s0; sm1[t] = s1;
    __syncthreads();
    #pragma unroll
    for (int s = 128; s > 0; s >>= 1) {
        if (t < s) { sm0[t] += sm0[t + s]; sm1[t] += sm1[t + s]; }
        __syncthreads();
    }
    if (t == 0) {
        double v0 = sm0[0] + (double)N_NODES * (double)b2[0];
        double v1 = sm1[0] + (double)N_NODES * (double)b2[1];
        double m  = fmax(v0, v1);
        double e0 = exp(v0 - m), e1 = exp(v1 - m);
        double den = e0 + e1;
        out[0] = (float)(e0 / den);
        out[1] = (float)(e1 / den);
    }
}

// ---------------------------------------------------------------- launch
extern "C" void kernel_launch(void* const* d_in, const int* in_sizes, int n_in,
                              void* d_out, int out_size) {
    const float* x  = (const float*)d_in[0];
    const void*  ei = d_in[1];                 // int32 OR int64, detected on device
    const float* ew = (const float*)d_in[2];
    const float* W1 = (const float*)d_in[3];
    const float* b1 = (const float*)d_in[4];
    const float* W2 = (const float*)d_in[5];
    const float* b2 = (const float*)d_in[6];

    const int TB = 256;
    const int nodeBlocks = (N_NODES + TB - 1) / TB;        // 1954

    k_detect<<<1, 1>>>((const int*)ei);
    k_deg   <<<EDGE4_GRID, TB>>>(ei, (const float4*)ew);
    k_dis   <<<nodeBlocks, TB>>>(x);
    k_msg   <<<EDGE4_GRID, TB>>>(ei, (const float4*)ew);
    k_node  <<<NODE_GRID, NODE_TB>>>(x, W1, b1, W2);
    k_edge2 <<<EDGE4_GRID, TB>>>(ei, (const float4*)ew);
    k_final <<<1, 256>>>(b2, (float*)d_out);
}

// round 7
// speedup vs baseline: 1.4075x; 1.1531x over previous
#include <cuda_runtime.h>

#define N_NODES 500000
#define N_EDGES 16000000

#define NODE_TB 256
#define NODE_GRID 1024      // k_node blocks
#define NPART NODE_GRID

// ---- device scratch (no allocations allowed; __device__ statics only) ----
__device__ int    g_idx64;            // 1 if edge_index is int64, 0 if int32
__device__ float  g_deg[N_NODES];     // 1 + sum of incoming edge weights
__device__ float  g_dis[N_NODES];     // rsqrt(deg)
__device__ float  g_q[N_NODES];       // dis * x
__device__ float  g_acc[N_NODES];     // sum_{e->d} ew * q[src]
__device__ float  g_u[N_NODES];       // sum_{e from s} ew * dis[dst]
__device__ double g_part0[NPART];     // per-block partial sums, channel 0
__device__ double g_part1[NPART];     // per-block partial sums, channel 1

// ---------------------------------------------------------------- dtype detect
__global__ void k_detect(const int* __restrict__ eiw) {
    int all_zero = 1;
    #pragma unroll
    for (int k = 0; k < 8; k++) all_zero &= (eiw[2 * k + 1] == 0);
    g_idx64 = all_zero;
}

// ---------------------------------------------------------------- index fetch (4 at a time)
__device__ __forceinline__ void load_idx4(const void* ei, int row, int t,
                                          int& i0, int& i1, int& i2, int& i3) {
    if (!g_idx64) {
        int4 v = ((const int4*)ei)[(size_t)row * (N_EDGES / 4) + t];
        i0 = v.x; i1 = v.y; i2 = v.z; i3 = v.w;
    } else {
        const longlong2* p = (const longlong2*)((const long long*)ei + (size_t)row * N_EDGES);
        longlong2 a = p[2 * t];
        longlong2 b = p[2 * t + 1];
        i0 = (int)a.x; i1 = (int)a.y; i2 = (int)b.x; i3 = (int)b.y;
    }
}

// ---------------------------------------------------------------- init
__global__ void k_init() {
    int i = blockIdx.x * blockDim.x + threadIdx.x;
    if (i < N_NODES) { g_deg[i] = 1.0f; g_acc[i] = 0.0f; g_u[i] = 0.0f; }
}

// ---------------------------------------------------------------- pass 1: degree (4 edges/thread)
__global__ void k_deg(const void* __restrict__ ei, const float4* __restrict__ ew4) {
    int t = blockIdx.x * blockDim.x + threadIdx.x;   // t < N_EDGES/4 exactly
    float4 w = ew4[t];
    int d0, d1, d2, d3;
    load_idx4(ei, 1, t, d0, d1, d2, d3);
    if ((unsigned)d0 < N_NODES) atomicAdd(&g_deg[d0], w.x);
    if ((unsigned)d1 < N_NODES) atomicAdd(&g_deg[d1], w.y);
    if ((unsigned)d2 < N_NODES) atomicAdd(&g_deg[d2], w.z);
    if ((unsigned)d3 < N_NODES) atomicAdd(&g_deg[d3], w.w);
}

// ---------------------------------------------------------------- node: dis, q
__global__ void k_dis(const float* __restrict__ x) {
    int i = blockIdx.x * blockDim.x + threadIdx.x;
    if (i < N_NODES) {
        float s = rsqrtf(g_deg[i]);     // deg >= 1 (self-loop weight 1)
        g_dis[i] = s;
        g_q[i]   = s * x[i];
    }
}

// ---------------------------------------------------------------- pass 2: acc[d] += ew * q[s] (4 edges/thread)
__global__ void k_msg(const void* __restrict__ ei, const float4* __restrict__ ew4) {
    int t = blockIdx.x * blockDim.x + threadIdx.x;
    float4 w = ew4[t];
    int s0, s1, s2, s3, d0, d1, d2, d3;
    load_idx4(ei, 0, t, s0, s1, s2, s3);
    load_idx4(ei, 1, t, d0, d1, d2, d3);
    // independent gathers first (overlap L2 latency), then REDs
    float q0 = ((unsigned)s0 < N_NODES) ? g_q[s0] : 0.0f;
    float q1 = ((unsigned)s1 < N_NODES) ? g_q[s1] : 0.0f;
    float q2 = ((unsigned)s2 < N_NODES) ? g_q[s2] : 0.0f;
    float q3 = ((unsigned)s3 < N_NODES) ? g_q[s3] : 0.0f;
    if ((unsigned)d0 < N_NODES) atomicAdd(&g_acc[d0], w.x * q0);
    if ((unsigned)d1 < N_NODES) atomicAdd(&g_acc[d1], w.y * q1);
    if ((unsigned)d2 < N_NODES) atomicAdd(&g_acc[d2], w.z * q2);
    if ((unsigned)d3 < N_NODES) atomicAdd(&g_acc[d3], w.w * q3);
}

// ---------------------------------------------------------------- pass 3: u[s] += ew * dis[d] (4 edges/thread)
__global__ void k_u(const void* __restrict__ ei, const float4* __restrict__ ew4) {
    int t = blockIdx.x * blockDim.x + threadIdx.x;
    float4 w = ew4[t];
    int s0, s1, s2, s3, d0, d1, d2, d3;
    load_idx4(ei, 0, t, s0, s1, s2, s3);
    load_idx4(ei, 1, t, d0, d1, d2, d3);
    float c0 = ((unsigned)d0 < N_NODES) ? g_dis[d0] : 0.0f;
    float c1 = ((unsigned)d1 < N_NODES) ? g_dis[d1] : 0.0f;
    float c2 = ((unsigned)d2 < N_NODES) ? g_dis[d2] : 0.0f;
    float c3 = ((unsigned)d3 < N_NODES) ? g_dis[d3] : 0.0f;
    if ((unsigned)s0 < N_NODES) atomicAdd(&g_u[s0], w.x * c0);
    if ((unsigned)s1 < N_NODES) atomicAdd(&g_u[s1], w.y * c1);
    if ((unsigned)s2 < N_NODES) atomicAdd(&g_u[s2], w.z * c2);
    if ((unsigned)s3 < N_NODES) atomicAdd(&g_u[s3], w.w * c3);
}

// ---------------------------------------------------------------- shared-mem double tree reduce
__device__ __forceinline__ void block_reduce_store(float a0, float a1, int slot) {
    __shared__ double sm0[NODE_TB], sm1[NODE_TB];
    int t = threadIdx.x;
    sm0[t] = (double)a0;
    sm1[t] = (double)a1;
    __syncthreads();
    #pragma unroll
    for (int s = NODE_TB / 2; s > 0; s >>= 1) {
        if (t < s) { sm0[t] += sm0[t + s]; sm1[t] += sm1[t + s]; }
        __syncthreads();
    }
    if (t == 0) { g_part0[slot] = sm0[0]; g_part1[slot] = sm1[0]; }
}

// ---------------------------------------------------------------- node: MLP + full per-node contribution
// contribution of node i to s[c]:  h2[i,c] * (1/deg_i + dis_i * u_i)
__global__ void k_node(const float* __restrict__ x, const float* __restrict__ W1,
                       const float* __restrict__ b1, const float* __restrict__ W2) {
    __shared__ float sW1[16], sb1[16], sW2[32];
    int t = threadIdx.x;
    if (t < 16) { sW1[t] = W1[t]; sb1[t] = b1[t]; }
    if (t < 32) sW2[t] = W2[t];
    __syncthreads();

    float a0 = 0.0f, a1 = 0.0f;
    int stride = gridDim.x * blockDim.x;
    for (int i = blockIdx.x * blockDim.x + t; i < N_NODES; i += stride) {
        float dis = g_dis[i];
        float inv = dis * dis;                     // 1/deg
        float agg = dis * g_acc[i] + x[i] * inv;   // layer-1 scalar aggregate
        float h0 = 0.0f, h1 = 0.0f;
        #pragma unroll
        for (int j = 0; j < 16; j++) {
            float h = fmaxf(fmaf(sW1[j], agg, sb1[j]), 0.0f);
            h0 = fmaf(h, sW2[2 * j],     h0);
            h1 = fmaf(h, sW2[2 * j + 1], h1);
        }
        float coef = fmaf(dis, g_u[i], inv);       // self + edge terms of final sum
        a0 = fmaf(coef, h0, a0);
        a1 = fmaf(coef, h1, a1);
    }
    block_reduce_store(a0, a1, blockIdx.x);
}

// ---------------------------------------------------------------- final: reduce partials, bias, softmax
__global__ void k_final(const float* __restrict__ b2, float* __restrict__ out) {
    __shared__ double sm0[256], sm1[256];
    int t = threadIdx.x;
    double s0 = 0.0, s1 = 0.0;
    for (int k = t; k < NPART; k += 256) { s0 += g_part0[k]; s1 += g_part1[k]; }
    sm0[t] = s0; sm1[t] = s1;
    __syncthreads();
    #pragma unroll
    for (int s = 128; s > 0; s >>= 1) {
        if (t < s) { sm0[t] += sm0[t + s]; sm1[t] += sm1[t + s]; }
        __syncthreads();
    }
    if (t == 0) {
        double v0 = sm0[0] + (double)N_NODES * (double)b2[0];
        double v1 = sm1[0] + (double)N_NODES * (double)b2[1];
        double m  = fmax(v0, v1);
        double e0 = exp(v0 - m), e1 = exp(v1 - m);
        double den = e0 + e1;
        out[0] = (float)(e0 / den);
        out[1] = (float)(e1 / den);
    }
}

// ---------------------------------------------------------------- launch
extern "C" void kernel_launch(void* const* d_in, const int* in_sizes, int n_in,
                              void* d_out, int out_size) {
    const float* x  = (const float*)d_in[0];
    const void*  ei = d_in[1];                 // int32 OR int64, detected on device
    const float* ew = (const float*)d_in[2];
    const float* W1 = (const float*)d_in[3];
    const float* b1 = (const float*)d_in[4];
    const float* W2 = (const float*)d_in[5];
    const float* b2 = (const float*)d_in[6];

    const int TB = 256;
    const int nodeBlocks  = (N_NODES + TB - 1) / TB;        // 1954
    const int edge4Blocks = (N_EDGES / 4) / TB;             // 15625 exact

    k_detect<<<1, 1>>>((const int*)ei);
    k_init  <<<nodeBlocks, TB>>>();
    k_deg   <<<edge4Blocks, TB>>>(ei, (const float4*)ew);
    k_dis   <<<nodeBlocks, TB>>>(x);
    k_msg   <<<edge4Blocks, TB>>>(ei, (const float4*)ew);
    k_u     <<<edge4Blocks, TB>>>(ei, (const float4*)ew);
    k_node  <<<NODE_GRID, NODE_TB>>>(x, W1, b1, W2);
    k_final <<<1, 256>>>(b2, (float*)d_out);
}